// round 1
// baseline (speedup 1.0000x reference)
#include <cuda_runtime.h>
#include <math.h>

#define Bc 8
#define Nc 1024
#define Mc 2048
#define Dc 1024

// ---------------------------------------------------------------------------
// Kernel 1: scores[b,n,m] = (text[b,n,:] . audio[b,m,:]) / sqrt(D)
//                           - (n/N - m/M)^2 / (2 s^2)
// 64x64 block tile, 4x4 per-thread microtile, K-tile = 16, fp32.
// Writes raw biased scores into attn buffer (masking handled by softmax pass).
// ---------------------------------------------------------------------------
__global__ __launch_bounds__(256) void gemm_scores(
    const float* __restrict__ text,
    const float* __restrict__ audio,
    const float* __restrict__ sigma,
    float* __restrict__ attn)
{
    __shared__ float Ts[64][17];   // text tile  [n][k], padded
    __shared__ float As[64][17];   // audio tile [m][k], padded

    const int b  = blockIdx.z;
    const int n0 = blockIdx.y * 64;
    const int m0 = blockIdx.x * 64;
    const int tid = threadIdx.x;
    const int tx = tid & 15;       // m direction
    const int ty = tid >> 4;       // n direction

    const float* Tb = text  + (size_t)b * Nc * Dc;
    const float* Ab = audio + (size_t)b * Mc * Dc;

    const int lrow = tid >> 2;     // 0..63
    const int lseg = (tid & 3) * 4;

    float acc[4][4];
    #pragma unroll
    for (int i = 0; i < 4; i++)
        #pragma unroll
        for (int j = 0; j < 4; j++) acc[i][j] = 0.0f;

    for (int k0 = 0; k0 < Dc; k0 += 16) {
        float4 tv = *(const float4*)(Tb + (size_t)(n0 + lrow) * Dc + k0 + lseg);
        float4 av = *(const float4*)(Ab + (size_t)(m0 + lrow) * Dc + k0 + lseg);
        Ts[lrow][lseg + 0] = tv.x; Ts[lrow][lseg + 1] = tv.y;
        Ts[lrow][lseg + 2] = tv.z; Ts[lrow][lseg + 3] = tv.w;
        As[lrow][lseg + 0] = av.x; As[lrow][lseg + 1] = av.y;
        As[lrow][lseg + 2] = av.z; As[lrow][lseg + 3] = av.w;
        __syncthreads();

        #pragma unroll
        for (int kk = 0; kk < 16; kk++) {
            float ra[4], rb[4];
            #pragma unroll
            for (int i = 0; i < 4; i++) ra[i] = Ts[ty * 4 + i][kk];
            #pragma unroll
            for (int j = 0; j < 4; j++) rb[j] = As[tx * 4 + j][kk];
            #pragma unroll
            for (int i = 0; i < 4; i++)
                #pragma unroll
                for (int j = 0; j < 4; j++)
                    acc[i][j] = fmaf(ra[i], rb[j], acc[i][j]);
        }
        __syncthreads();
    }

    const float s = fabsf(sigma[0]) + 1e-8f;
    const float inv2s2 = 1.0f / (2.0f * s * s);
    const float scale = 0.03125f;  // 1/sqrt(1024)

    #pragma unroll
    for (int i = 0; i < 4; i++) {
        const int n = n0 + ty * 4 + i;
        float* row = attn + ((size_t)b * Nc + n) * Mc;
        const float npos = (float)n * (1.0f / Nc);
        #pragma unroll
        for (int j = 0; j < 4; j++) {
            const int m = m0 + tx * 4 + j;
            const float dd = npos - (float)m * (1.0f / Mc);
            row[m] = acc[i][j] * scale - dd * dd * inv2s2;
        }
    }
}

// ---------------------------------------------------------------------------
// Kernel 2: per-row masked softmax over M=2048. One block per (b,n) row.
// Masked (j >= len) entries become exactly 0.
// ---------------------------------------------------------------------------
__global__ __launch_bounds__(256) void softmax_rows(
    float* __restrict__ attn,
    const int* __restrict__ lens)
{
    const int row = blockIdx.x;        // b*N + n
    const int b = row >> 10;           // row / 1024
    const int len = lens[b];
    float* P = attn + (size_t)row * Mc;
    const int tid = threadIdx.x;

    __shared__ float red[256];

    float vals[8];
    float mx = -INFINITY;
    #pragma unroll
    for (int t = 0; t < 8; t++) {
        const int j = tid + t * 256;
        const float v = (j < len) ? P[j] : -INFINITY;
        vals[t] = v;
        mx = fmaxf(mx, v);
    }
    red[tid] = mx;
    __syncthreads();
    #pragma unroll
    for (int s = 128; s > 0; s >>= 1) {
        if (tid < s) red[tid] = fmaxf(red[tid], red[tid + s]);
        __syncthreads();
    }
    mx = red[0];
    __syncthreads();

    float sum = 0.0f;
    #pragma unroll
    for (int t = 0; t < 8; t++) {
        const int j = tid + t * 256;
        const float e = (j < len) ? expf(vals[t] - mx) : 0.0f;
        vals[t] = e;
        sum += e;
    }
    red[tid] = sum;
    __syncthreads();
    #pragma unroll
    for (int s = 128; s > 0; s >>= 1) {
        if (tid < s) red[tid] += red[tid + s];
        __syncthreads();
    }
    const float inv = 1.0f / red[0];

    #pragma unroll
    for (int t = 0; t < 8; t++) {
        const int j = tid + t * 256;
        P[j] = vals[t] * inv;
    }
}

// ---------------------------------------------------------------------------
// Kernel 3: enhanced[b,n,d] = sum_m attn[b,n,m] * audio[b,m,d]
// 64(n) x 64(d) tile, K(=m)-tile = 16, 4x4 microtile, fp32.
// ---------------------------------------------------------------------------
__global__ __launch_bounds__(256) void gemm_out(
    const float* __restrict__ attn,
    const float* __restrict__ audio,
    float* __restrict__ outp)
{
    __shared__ float Ps[64][17];   // attn tile  [n][m]
    __shared__ float Av[16][64];   // audio tile [m][d]

    const int b  = blockIdx.z;
    const int n0 = blockIdx.y * 64;
    const int d0 = blockIdx.x * 64;
    const int tid = threadIdx.x;
    const int tx = tid & 15;       // d direction
    const int ty = tid >> 4;       // n direction

    const float* Ab = audio + (size_t)b * Mc * Dc;

    const int lrow = tid >> 2;
    const int lseg = (tid & 3) * 4;
    const int arow = tid >> 4;          // 0..15
    const int acol = (tid & 15) * 4;    // 0..60

    float acc[4][4];
    #pragma unroll
    for (int i = 0; i < 4; i++)
        #pragma unroll
        for (int j = 0; j < 4; j++) acc[i][j] = 0.0f;

    for (int k0 = 0; k0 < Mc; k0 += 16) {
        float4 pv = *(const float4*)(attn + ((size_t)b * Nc + n0 + lrow) * Mc + k0 + lseg);
        Ps[lrow][lseg + 0] = pv.x; Ps[lrow][lseg + 1] = pv.y;
        Ps[lrow][lseg + 2] = pv.z; Ps[lrow][lseg + 3] = pv.w;
        float4 av = *(const float4*)(Ab + (size_t)(k0 + arow) * Dc + d0 + acol);
        *(float4*)&Av[arow][acol] = av;
        __syncthreads();

        #pragma unroll
        for (int kk = 0; kk < 16; kk++) {
            float ra[4];
            #pragma unroll
            for (int i = 0; i < 4; i++) ra[i] = Ps[ty * 4 + i][kk];
            float4 rbv = *(const float4*)&Av[kk][tx * 4];
            float rb[4] = {rbv.x, rbv.y, rbv.z, rbv.w};
            #pragma unroll
            for (int i = 0; i < 4; i++)
                #pragma unroll
                for (int j = 0; j < 4; j++)
                    acc[i][j] = fmaf(ra[i], rb[j], acc[i][j]);
        }
        __syncthreads();
    }

    #pragma unroll
    for (int i = 0; i < 4; i++) {
        const int n = n0 + ty * 4 + i;
        float4 v = make_float4(acc[i][0], acc[i][1], acc[i][2], acc[i][3]);
        *(float4*)(outp + ((size_t)b * Nc + n) * Dc + d0 + tx * 4) = v;
    }
}

// ---------------------------------------------------------------------------
extern "C" void kernel_launch(void* const* d_in, const int* in_sizes, int n_in,
                              void* d_out, int out_size)
{
    const float* text  = (const float*)d_in[0];
    const float* audio = (const float*)d_in[1];
    const float* sigma = (const float*)d_in[2];
    const int*   lens  = (const int*)d_in[3];

    float* enhanced = (float*)d_out;                       // B*N*D
    float* attn     = enhanced + (size_t)Bc * Nc * Dc;     // B*N*M

    gemm_scores<<<dim3(Mc / 64, Nc / 64, Bc), 256>>>(text, audio, sigma, attn);
    softmax_rows<<<Bc * Nc, 256>>>(attn, lens);
    gemm_out<<<dim3(Dc / 64, Nc / 64, Bc), 256>>>(attn, audio, enhanced);
}

// round 3
// speedup vs baseline: 4.0269x; 4.0269x over previous
#include <cuda_runtime.h>
#include <math.h>
#include <stdint.h>

#define Bc 8
#define Nc 1024
#define Mc 2048
#define Dc 1024

// Scratch (allocation-free rule): rounded operands + transposed audio
__device__ float g_audioT[(size_t)Bc * Dc * Mc];   // [b][d][m], tf32-rounded
__device__ float g_audioR[(size_t)Bc * Mc * Dc];   // [b][m][d], tf32-rounded
__device__ float g_textR [(size_t)Bc * Nc * Dc];   // [b][n][d], tf32-rounded

__device__ __forceinline__ float tf32r(float x) {
    uint32_t u;
    asm("cvt.rna.tf32.f32 %0, %1;" : "=r"(u) : "f"(x));
    return __uint_as_float(u);
}
__device__ __forceinline__ void cp_async16(uint32_t dst, const void* src) {
    asm volatile("cp.async.cg.shared.global [%0], [%1], 16;" :: "r"(dst), "l"(src) : "memory");
}
__device__ __forceinline__ void mma_tf32(float* c, const uint32_t* a, const uint32_t* b) {
    asm volatile(
        "mma.sync.aligned.m16n8k8.row.col.f32.tf32.tf32.f32 "
        "{%0,%1,%2,%3}, {%4,%5,%6,%7}, {%8,%9}, {%0,%1,%2,%3};"
        : "+f"(c[0]), "+f"(c[1]), "+f"(c[2]), "+f"(c[3])
        : "r"(a[0]), "r"(a[1]), "r"(a[2]), "r"(a[3]), "r"(b[0]), "r"(b[1]));
}

#define BM 128
#define BN 128
#define BK 32
#define BKP 36                       // padded k-stride (floats): conflict-free
#define STAGE_F (BM*BKP + BN*BKP)    // 9216 floats per stage
#define SMEM_BYTES (2 * STAGE_F * 4) // 73728 B, double buffered

// ---------------------------------------------------------------------------
// tf32 tensor-core GEMM: D[128 x 128] = A[128 x K] . B[128 x K]^T per tile.
// A rows = out rows (n); B rows = out cols (m or d); both K-major fp32
// (already tf32-rounded). BIAS fuses the Gaussian positional bias (GEMM1).
// ---------------------------------------------------------------------------
template<int KTOT, bool BIAS>
__global__ __launch_bounds__(256, 2) void tc_gemm(
    const float* __restrict__ Ag, const float* __restrict__ Bg,
    float* __restrict__ Og,
    size_t sA, size_t sB, size_t sO,    // batch strides (elements)
    int ldA, int ldB, int ldO,          // row strides (elements)
    const float* __restrict__ sigma)
{
    extern __shared__ float sm[];
    const uint32_t smemU = (uint32_t)__cvta_generic_to_shared(sm);
    const int tid  = threadIdx.x;
    const int lane = tid & 31;
    const int wid  = tid >> 5;
    const int wm0  = (wid & 3) * 32;    // warp m offset in tile
    const int wn0  = (wid >> 2) * 64;   // warp n offset in tile
    const int gq   = lane >> 2;         // groupID
    const int tg   = lane & 3;          // thread in group

    const int b  = blockIdx.z;
    const int r0 = blockIdx.y * BM;
    const int c0 = blockIdx.x * BN;

    const float* Ab = Ag + (size_t)b * sA + (size_t)r0 * ldA;
    const float* Bb = Bg + (size_t)b * sB + (size_t)c0 * ldB;

    float acc[2][8][4];
    #pragma unroll
    for (int mt = 0; mt < 2; ++mt)
        #pragma unroll
        for (int nt = 0; nt < 8; ++nt)
            #pragma unroll
            for (int r = 0; r < 4; ++r) acc[mt][nt][r] = 0.0f;

    auto issue = [&](int c) {
        const int s  = c & 1;
        const int k0 = c * BK;
        #pragma unroll
        for (int i = 0; i < 8; ++i) {
            const int q    = tid + i * 256;       // 0..2047
            const int isB  = q >> 10;
            const int qq   = q & 1023;
            const int row  = qq >> 3;
            const int segf = (qq & 7) * 4;        // float col within BK
            const float* src = (isB ? Bb : Ab)
                             + (size_t)row * (isB ? ldB : ldA) + k0 + segf;
            const uint32_t dst = smemU +
                (uint32_t)(s * STAGE_F + isB * (BM * BKP) + row * BKP + segf) * 4u;
            cp_async16(dst, src);
        }
        asm volatile("cp.async.commit_group;" ::: "memory");
    };

    constexpr int NST = KTOT / BK;
    issue(0);
    for (int c = 0; c < NST; ++c) {
        if (c + 1 < NST) {
            issue(c + 1);
            asm volatile("cp.async.wait_group 1;" ::: "memory");
        } else {
            asm volatile("cp.async.wait_group 0;" ::: "memory");
        }
        __syncthreads();

        const float* As = sm + (c & 1) * STAGE_F;
        const float* Bs = As + BM * BKP;

        #pragma unroll
        for (int ks = 0; ks < 4; ++ks) {
            const int kc = ks * 8 + tg;
            uint32_t af[2][4], bf[8][2];
            #pragma unroll
            for (int mt = 0; mt < 2; ++mt) {
                const int r = wm0 + mt * 16 + gq;
                af[mt][0] = __float_as_uint(As[r * BKP + kc]);
                af[mt][1] = __float_as_uint(As[(r + 8) * BKP + kc]);
                af[mt][2] = __float_as_uint(As[r * BKP + kc + 4]);
                af[mt][3] = __float_as_uint(As[(r + 8) * BKP + kc + 4]);
            }
            #pragma unroll
            for (int nt = 0; nt < 8; ++nt) {
                const int nr = wn0 + nt * 8 + gq;
                bf[nt][0] = __float_as_uint(Bs[nr * BKP + kc]);
                bf[nt][1] = __float_as_uint(Bs[nr * BKP + kc + 4]);
            }
            #pragma unroll
            for (int mt = 0; mt < 2; ++mt)
                #pragma unroll
                for (int nt = 0; nt < 8; ++nt)
                    mma_tf32(acc[mt][nt], af[mt], bf[nt]);
        }
        __syncthreads();
    }

    // ------------------------------------------------------------------ epi
    float inv2s2 = 0.f;
    if (BIAS) {
        const float s = fabsf(sigma[0]) + 1e-8f;
        inv2s2 = 1.0f / (2.0f * s * s);
    }

    #pragma unroll
    for (int mt = 0; mt < 2; ++mt) {
        #pragma unroll
        for (int h = 0; h < 2; ++h) {
            const int rn = r0 + wm0 + mt * 16 + gq + h * 8;
            float* orow = Og + (size_t)b * sO + (size_t)rn * ldO;
            const float npos = (float)rn * (1.0f / Nc);
            #pragma unroll
            for (int nt = 0; nt < 8; ++nt) {
                const int cn = c0 + wn0 + nt * 8 + 2 * tg;
                float2 v = make_float2(acc[mt][nt][h * 2 + 0],
                                       acc[mt][nt][h * 2 + 1]);
                if (BIAS) {
                    const float d0 = npos - (float)(cn + 0) * (1.0f / Mc);
                    const float d1 = npos - (float)(cn + 1) * (1.0f / Mc);
                    v.x = v.x * 0.03125f - d0 * d0 * inv2s2;
                    v.y = v.y * 0.03125f - d1 * d1 * inv2s2;
                }
                *(float2*)(orow + cn) = v;
            }
        }
    }
}

// ---------------------------------------------------------------------------
// Round text to tf32 (rna) into g_textR
// ---------------------------------------------------------------------------
__global__ __launch_bounds__(256) void round_text(const float* __restrict__ in)
{
    const size_t i = ((size_t)blockIdx.x * 256 + threadIdx.x) * 4;
    float4 v = *(const float4*)(in + i);
    v.x = tf32r(v.x); v.y = tf32r(v.y); v.z = tf32r(v.z); v.w = tf32r(v.w);
    *(float4*)(g_textR + i) = v;
}

// ---------------------------------------------------------------------------
// audio -> g_audioR (rounded, same layout) + g_audioT (rounded, transposed)
// ---------------------------------------------------------------------------
__global__ __launch_bounds__(256) void prep_audio(const float* __restrict__ audio)
{
    __shared__ float t[32][33];
    const int b  = blockIdx.z;
    const int m0 = blockIdx.x * 32;
    const int d0 = blockIdx.y * 32;
    const int tx = threadIdx.x & 31;
    const int ty = threadIdx.x >> 5;     // 0..7

    const float* src = audio + (size_t)b * Mc * Dc;
    float* dstR = g_audioR + (size_t)b * Mc * Dc;
    #pragma unroll
    for (int i = 0; i < 4; ++i) {
        const int m = m0 + ty + i * 8;
        const float v = tf32r(src[(size_t)m * Dc + d0 + tx]);
        t[ty + i * 8][tx] = v;
        dstR[(size_t)m * Dc + d0 + tx] = v;
    }
    __syncthreads();
    float* dstT = g_audioT + (size_t)b * Dc * Mc;
    #pragma unroll
    for (int i = 0; i < 4; ++i)
        dstT[(size_t)(d0 + ty + i * 8) * Mc + m0 + tx] = t[tx][ty + i * 8];
}

// ---------------------------------------------------------------------------
// Masked row softmax over M=2048; one block per (b,n) row. tf32-rounded store.
// ---------------------------------------------------------------------------
__global__ __launch_bounds__(256) void softmax_rows(
    float* __restrict__ attn, const int* __restrict__ lens)
{
    const int row = blockIdx.x;
    const int b = row >> 10;
    const int len = lens[b];
    float* P = attn + (size_t)row * Mc;
    const int tid = threadIdx.x;

    __shared__ float red[256];

    float vals[8];
    float mx = -INFINITY;
    #pragma unroll
    for (int t = 0; t < 8; t++) {
        const int j = tid + t * 256;
        const float v = (j < len) ? P[j] : -INFINITY;
        vals[t] = v;
        mx = fmaxf(mx, v);
    }
    red[tid] = mx;
    __syncthreads();
    #pragma unroll
    for (int s = 128; s > 0; s >>= 1) {
        if (tid < s) red[tid] = fmaxf(red[tid], red[tid + s]);
        __syncthreads();
    }
    mx = red[0];
    __syncthreads();

    float sum = 0.0f;
    #pragma unroll
    for (int t = 0; t < 8; t++) {
        const int j = tid + t * 256;
        const float e = (j < len) ? expf(vals[t] - mx) : 0.0f;
        vals[t] = e;
        sum += e;
    }
    red[tid] = sum;
    __syncthreads();
    #pragma unroll
    for (int s = 128; s > 0; s >>= 1) {
        if (tid < s) red[tid] += red[tid + s];
        __syncthreads();
    }
    const float inv = 1.0f / red[0];

    #pragma unroll
    for (int t = 0; t < 8; t++) {
        const int j = tid + t * 256;
        P[j] = tf32r(vals[t] * inv);
    }
}

// ---------------------------------------------------------------------------
extern "C" void kernel_launch(void* const* d_in, const int* in_sizes, int n_in,
                              void* d_out, int out_size)
{
    const float* text  = (const float*)d_in[0];
    const float* audio = (const float*)d_in[1];
    const float* sigma = (const float*)d_in[2];
    const int*   lens  = (const int*)d_in[3];

    float* enhanced = (float*)d_out;                    // B*N*D
    float* attn     = enhanced + (size_t)Bc * Nc * Dc;  // B*N*M (also scores)

    void *audioT_p = nullptr, *audioR_p = nullptr, *textR_p = nullptr;
    cudaGetSymbolAddress(&audioT_p, g_audioT);
    cudaGetSymbolAddress(&audioR_p, g_audioR);
    cudaGetSymbolAddress(&textR_p,  g_textR);

    cudaFuncSetAttribute(tc_gemm<Dc, true>,
                         cudaFuncAttributeMaxDynamicSharedMemorySize, SMEM_BYTES);
    cudaFuncSetAttribute(tc_gemm<Mc, false>,
                         cudaFuncAttributeMaxDynamicSharedMemorySize, SMEM_BYTES);

    round_text<<<(Bc * Nc * Dc) / (256 * 4), 256>>>(text);
    prep_audio<<<dim3(Mc / 32, Dc / 32, Bc), 256>>>(audio);

    // GEMM1: scores = textR . audioR^T (+bias) -> attn
    tc_gemm<Dc, true><<<dim3(Mc / 128, Nc / 128, Bc), 256, SMEM_BYTES>>>(
        (const float*)textR_p, (const float*)audioR_p, attn,
        (size_t)Nc * Dc, (size_t)Mc * Dc, (size_t)Nc * Mc,
        Dc, Dc, Mc, sigma);

    softmax_rows<<<Bc * Nc, 256>>>(attn, lens);

    // GEMM2: enhanced = attn . audio (via audioT, K-major over m)
    tc_gemm<Mc, false><<<dim3(Dc / 128, Nc / 128, Bc), 256, SMEM_BYTES>>>(
        attn, (const float*)audioT_p, enhanced,
        (size_t)Nc * Mc, (size_t)Dc * Mc, (size_t)Nc * Dc,
        Mc, Mc, Dc, nullptr);
}

// round 5
// speedup vs baseline: 4.1954x; 1.0418x over previous
#include <cuda_runtime.h>
#include <math.h>
#include <stdint.h>

#define Bc 8
#define Nc 1024
#define Mc 2048
#define Dc 1024

// Scratch (allocation-free rule): tf32-rounded operands
__device__ float g_audioR[(size_t)Bc * Mc * Dc];   // [b][m][d], tf32-rounded
__device__ float g_textR [(size_t)Bc * Nc * Dc];   // [b][n][d], tf32-rounded

__device__ __forceinline__ float tf32r(float x) {
    uint32_t u;
    asm("cvt.rna.tf32.f32 %0, %1;" : "=r"(u) : "f"(x));
    return __uint_as_float(u);
}
__device__ __forceinline__ void cp_async16(uint32_t dst, const void* src) {
    asm volatile("cp.async.cg.shared.global [%0], [%1], 16;" :: "r"(dst), "l"(src) : "memory");
}
__device__ __forceinline__ void mma_tf32(float* c, const uint32_t* a, const uint32_t* b) {
    asm volatile(
        "mma.sync.aligned.m16n8k8.row.col.f32.tf32.tf32.f32 "
        "{%0,%1,%2,%3}, {%4,%5,%6,%7}, {%8,%9}, {%0,%1,%2,%3};"
        : "+f"(c[0]), "+f"(c[1]), "+f"(c[2]), "+f"(c[3])
        : "r"(a[0]), "r"(a[1]), "r"(a[2]), "r"(a[3]), "r"(b[0]), "r"(b[1]));
}

#define BM 128
#define BN 128
#define BK 32
#define AKP 36     // A smem k-stride (floats), conflict-free
#define BKP 36     // B K-major smem k-stride
#define BNP 136    // B row-major-by-k smem n-stride (kc*136 %32 = 8*kc: CF)

// ---------------------------------------------------------------------------
// tf32 tensor-core GEMM: D[128 x 128] = A[128 x K] . op(B) per CTA tile.
//   BROW=false: B stored [col][k] K-major (B rows = out cols), gemm1 style
//   BROW=true : B stored [k][col] row-major-by-k (audio direct), gemm2 style
// 3-stage cp.async pipeline, one __syncthreads per K-stage.
// BIAS fuses /sqrt(D) + Gaussian positional bias (gemm1 -> scores).
// ---------------------------------------------------------------------------
template<int KTOT, bool BIAS, bool BROW>
__global__ __launch_bounds__(256, 2) void tc_gemm(
    const float* __restrict__ Ag, const float* __restrict__ Bg,
    float* __restrict__ Og,
    size_t sA, size_t sB, size_t sO,    // batch strides (elements)
    int ldA, int ldB, int ldO,          // row strides (elements)
    const float* __restrict__ sigma)
{
    constexpr int A_F   = BM * AKP;                      // 4608 floats
    constexpr int B_F   = BROW ? (BK * BNP) : (BN * BKP);
    constexpr int STAGE = A_F + B_F;

    extern __shared__ float sm[];
    const uint32_t smemU = (uint32_t)__cvta_generic_to_shared(sm);
    const int tid  = threadIdx.x;
    const int lane = tid & 31;
    const int wid  = tid >> 5;
    const int wm0  = (wid & 3) * 32;    // warp row offset
    const int wn0  = (wid >> 2) * 64;   // warp col offset
    const int gq   = lane >> 2;
    const int tg   = lane & 3;

    const int b  = blockIdx.z;
    const int r0 = blockIdx.y * BM;
    const int c0 = blockIdx.x * BN;

    const float* Ab = Ag + (size_t)b * sA + (size_t)r0 * ldA;
    // BROW=false: Bb points at row c0 (rows are out-cols). BROW=true: col offset c0.
    const float* Bb = Bg + (size_t)b * sB + (BROW ? (size_t)c0 : (size_t)c0 * ldB);

    float acc[2][8][4];
    #pragma unroll
    for (int mt = 0; mt < 2; ++mt)
        #pragma unroll
        for (int nt = 0; nt < 8; ++nt)
            #pragma unroll
            for (int r = 0; r < 4; ++r) acc[mt][nt][r] = 0.0f;

    auto issue = [&](int c) {
        const int s  = c % 3;
        const int k0 = c * BK;
        #pragma unroll
        for (int i = 0; i < 8; ++i) {
            const int q   = tid + i * 256;    // 0..2047
            const int isB = q >> 10;
            const int qq  = q & 1023;
            const float* src;
            uint32_t off;
            if (!isB) {
                const int row = qq >> 3, segf = (qq & 7) * 4;
                src = Ab + (size_t)row * ldA + k0 + segf;
                off = (uint32_t)(row * AKP + segf);
            } else if (!BROW) {
                const int row = qq >> 3, segf = (qq & 7) * 4;
                src = Bb + (size_t)row * ldB + k0 + segf;
                off = (uint32_t)(A_F + row * BKP + segf);
            } else {
                const int kr = qq >> 5, df = (qq & 31) * 4;
                src = Bb + (size_t)(k0 + kr) * ldB + df;
                off = (uint32_t)(A_F + kr * BNP + df);
            }
            cp_async16(smemU + (uint32_t)(s * STAGE + off) * 4u, src);
        }
        asm volatile("cp.async.commit_group;" ::: "memory");
    };

    constexpr int NST = KTOT / BK;
    issue(0);
    issue(1);
    for (int c = 0; c < NST; ++c) {
        if (c + 1 < NST) asm volatile("cp.async.wait_group 1;" ::: "memory");
        else             asm volatile("cp.async.wait_group 0;" ::: "memory");
        __syncthreads();
        if (c + 2 < NST) issue(c + 2);

        const float* As = sm + (c % 3) * STAGE;
        const float* Bs = As + A_F;

        #pragma unroll
        for (int ks = 0; ks < 4; ++ks) {
            const int kc = ks * 8 + tg;
            uint32_t af[2][4], bf[8][2];
            #pragma unroll
            for (int mt = 0; mt < 2; ++mt) {
                const int r = wm0 + mt * 16 + gq;
                af[mt][0] = __float_as_uint(As[r * AKP + kc]);
                af[mt][1] = __float_as_uint(As[(r + 8) * AKP + kc]);
                af[mt][2] = __float_as_uint(As[r * AKP + kc + 4]);
                af[mt][3] = __float_as_uint(As[(r + 8) * AKP + kc + 4]);
            }
            #pragma unroll
            for (int nt = 0; nt < 8; ++nt) {
                const int nr = wn0 + nt * 8 + gq;
                if (!BROW) {
                    bf[nt][0] = __float_as_uint(Bs[nr * BKP + kc]);
                    bf[nt][1] = __float_as_uint(Bs[nr * BKP + kc + 4]);
                } else {
                    bf[nt][0] = __float_as_uint(Bs[kc * BNP + nr]);
                    bf[nt][1] = __float_as_uint(Bs[(kc + 4) * BNP + nr]);
                }
            }
            #pragma unroll
            for (int mt = 0; mt < 2; ++mt)
                #pragma unroll
                for (int nt = 0; nt < 8; ++nt)
                    mma_tf32(acc[mt][nt], af[mt], bf[nt]);
        }
    }

    // ------------------------------------------------------------------ epi
    float inv2s2 = 0.f;
    if (BIAS) {
        const float s = fabsf(sigma[0]) + 1e-8f;
        inv2s2 = 1.0f / (2.0f * s * s);
    }

    #pragma unroll
    for (int mt = 0; mt < 2; ++mt) {
        #pragma unroll
        for (int h = 0; h < 2; ++h) {
            const int rn = r0 + wm0 + mt * 16 + gq + h * 8;
            float* orow = Og + (size_t)b * sO + (size_t)rn * ldO;
            const float npos = (float)rn * (1.0f / Nc);
            #pragma unroll
            for (int nt = 0; nt < 8; ++nt) {
                const int cn = c0 + wn0 + nt * 8 + 2 * tg;
                float2 v = make_float2(acc[mt][nt][h * 2 + 0],
                                       acc[mt][nt][h * 2 + 1]);
                if (BIAS) {
                    const float d0 = npos - (float)(cn + 0) * (1.0f / Mc);
                    const float d1 = npos - (float)(cn + 1) * (1.0f / Mc);
                    v.x = v.x * 0.03125f - d0 * d0 * inv2s2;
                    v.y = v.y * 0.03125f - d1 * d1 * inv2s2;
                }
                *(float2*)(orow + cn) = v;
            }
        }
    }
}

// ---------------------------------------------------------------------------
// Round to tf32 (rna), streaming. count must be /1024.
// ---------------------------------------------------------------------------
__global__ __launch_bounds__(256) void round_tf32(
    const float* __restrict__ in, float* __restrict__ out)
{
    const size_t i = ((size_t)blockIdx.x * 256 + threadIdx.x) * 4;
    float4 v = *(const float4*)(in + i);
    v.x = tf32r(v.x); v.y = tf32r(v.y); v.z = tf32r(v.z); v.w = tf32r(v.w);
    *(float4*)(out + i) = v;
}

// ---------------------------------------------------------------------------
// Masked row softmax over M=2048; one block of 256 per (b,n) row.
// float4 I/O, warp-shuffle reductions, __expf, tf32-rounded store.
// ---------------------------------------------------------------------------
__global__ __launch_bounds__(256) void softmax_rows(
    float* __restrict__ attn, const int* __restrict__ lens)
{
    const int row = blockIdx.x;
    const int b = row >> 10;
    const int len = lens[b];
    float* P = attn + (size_t)row * Mc;
    const int tid  = threadIdx.x;
    const int lane = tid & 31;
    const int wrp  = tid >> 5;

    __shared__ float red[8];

    float4 v0 = *(const float4*)(P + tid * 4);
    float4 v1 = *(const float4*)(P + 1024 + tid * 4);
    const int j0 = tid * 4, j1 = 1024 + tid * 4;

    float vals[8] = {
        (j0 + 0 < len) ? v0.x : -INFINITY, (j0 + 1 < len) ? v0.y : -INFINITY,
        (j0 + 2 < len) ? v0.z : -INFINITY, (j0 + 3 < len) ? v0.w : -INFINITY,
        (j1 + 0 < len) ? v1.x : -INFINITY, (j1 + 1 < len) ? v1.y : -INFINITY,
        (j1 + 2 < len) ? v1.z : -INFINITY, (j1 + 3 < len) ? v1.w : -INFINITY };

    float mx = vals[0];
    #pragma unroll
    for (int t = 1; t < 8; ++t) mx = fmaxf(mx, vals[t]);
    #pragma unroll
    for (int o = 16; o > 0; o >>= 1) mx = fmaxf(mx, __shfl_xor_sync(~0u, mx, o));
    if (lane == 0) red[wrp] = mx;
    __syncthreads();
    {
        float t = red[lane & 7];
        #pragma unroll
        for (int o = 4; o > 0; o >>= 1) t = fmaxf(t, __shfl_xor_sync(~0u, t, o));
        mx = t;
    }

    float sum = 0.0f;
    #pragma unroll
    for (int t = 0; t < 8; ++t) {
        const float e = (vals[t] == -INFINITY) ? 0.0f : __expf(vals[t] - mx);
        vals[t] = e;
        sum += e;
    }
    #pragma unroll
    for (int o = 16; o > 0; o >>= 1) sum += __shfl_xor_sync(~0u, sum, o);
    __syncthreads();
    if (lane == 0) red[wrp] = sum;
    __syncthreads();
    {
        float t = red[lane & 7];
        #pragma unroll
        for (int o = 4; o > 0; o >>= 1) t += __shfl_xor_sync(~0u, t, o);
        sum = t;
    }
    const float inv = 1.0f / sum;

    v0.x = tf32r(vals[0] * inv); v0.y = tf32r(vals[1] * inv);
    v0.z = tf32r(vals[2] * inv); v0.w = tf32r(vals[3] * inv);
    v1.x = tf32r(vals[4] * inv); v1.y = tf32r(vals[5] * inv);
    v1.z = tf32r(vals[6] * inv); v1.w = tf32r(vals[7] * inv);
    *(float4*)(P + tid * 4) = v0;
    *(float4*)(P + 1024 + tid * 4) = v1;
}

// ---------------------------------------------------------------------------
extern "C" void kernel_launch(void* const* d_in, const int* in_sizes, int n_in,
                              void* d_out, int out_size)
{
    const float* text  = (const float*)d_in[0];
    const float* audio = (const float*)d_in[1];
    const float* sigma = (const float*)d_in[2];
    const int*   lens  = (const int*)d_in[3];

    float* enhanced = (float*)d_out;                    // B*N*D
    float* attn     = enhanced + (size_t)Bc * Nc * Dc;  // B*N*M (scores scratch)

    void *audioR_p = nullptr, *textR_p = nullptr;
    cudaGetSymbolAddress(&audioR_p, g_audioR);
    cudaGetSymbolAddress(&textR_p,  g_textR);

    constexpr int SM1 = 3 * (BM * AKP + BN * BKP) * 4;   // 110592 B
    constexpr int SM2 = 3 * (BM * AKP + BK * BNP) * 4;   // 107520 B
    cudaFuncSetAttribute(tc_gemm<Dc, true, false>,
                         cudaFuncAttributeMaxDynamicSharedMemorySize, SM1);
    cudaFuncSetAttribute(tc_gemm<Mc, false, true>,
                         cudaFuncAttributeMaxDynamicSharedMemorySize, SM2);

    round_tf32<<<(Bc * Nc * Dc) / 1024, 256>>>(text,  (float*)textR_p);
    round_tf32<<<(Bc * Mc * Dc) / 1024, 256>>>(audio, (float*)audioR_p);

    // GEMM1: scores = textR . audioR^T (+bias) -> attn
    tc_gemm<Dc, true, false><<<dim3(Mc / 128, Nc / 128, Bc), 256, SM1>>>(
        (const float*)textR_p, (const float*)audioR_p, attn,
        (size_t)Nc * Dc, (size_t)Mc * Dc, (size_t)Nc * Mc,
        Dc, Dc, Mc, sigma);

    softmax_rows<<<Bc * Nc, 256>>>(attn, lens);

    // GEMM2: enhanced = attn . audioR (B row-major-by-k, no transpose)
    tc_gemm<Mc, false, true><<<dim3(Dc / 128, Nc / 128, Bc), 256, SM2>>>(
        attn, (const float*)audioR_p, enhanced,
        (size_t)Nc * Mc, (size_t)Mc * Dc, (size_t)Nc * Dc,
        Mc, Dc, Dc, nullptr);
}